// round 14
// baseline (speedup 1.0000x reference)
#include <cuda_runtime.h>

#define NUM_OUTPUTS 1032
#define D4 258              // 1032 floats = 258 float4 per weight row
#define CHUNK 64            // float4 per column chunk; 4 chunks cover 256, +2 tail
#define NCHUNK 4
#define MAX_ACTIVE 32
#define BATCH 4096
#define THREADS 64          // 2 warps, all lanes active -> 32 CTAs/SM = 100% occ

__global__ __launch_bounds__(THREADS)
void ft_occ2_kernel(const int*    __restrict__ idx0,
                    const float*  __restrict__ val0,
                    const int*    __restrict__ idx1,
                    const float*  __restrict__ val1,
                    const float4* __restrict__ W4,
                    const float4* __restrict__ bias4,
                    float4*       __restrict__ out4)
{
    const int r     = blockIdx.x;          // 0..8191 : both feature sets fused
    const int chunk = blockIdx.y;          // 0..3    : slow dim -> L2 phases
    const int tid   = threadIdx.x;

    const int*   idx;
    const float* val;
    int row;
    if (r < BATCH) { idx = idx0; val = val0; row = r; }
    else           { idx = idx1; val = val1; row = r - BATCH; }

    // Packed (row offset in float4 units, value bits): one LDS.64 per k.
    __shared__ int2 sOV[MAX_ACTIVE];
    if (tid < MAX_ACTIVE) {
        sOV[tid] = make_int2(idx[row * MAX_ACTIVE + tid] * D4,
                             __float_as_int(val[row * MAX_ACTIVE + tid]));
    }
    __syncthreads();

    const int c = chunk * CHUNK + tid;     // float4 column index, 0..255
    const float4* __restrict__ Wc = W4 + c;
    float4* __restrict__ orow = out4 + (size_t)r * D4;

    float4 a = bias4[c];

    #pragma unroll 8
    for (int k = 0; k < MAX_ACTIVE; ++k) {
        const int2   ov = sOV[k];           // broadcast LDS.64
        const float4 w  = __ldg(Wc + ov.x);
        const float  v  = __int_as_float(ov.y);
        a.x = fmaf(w.x, v, a.x);
        a.y = fmaf(w.y, v, a.y);
        a.z = fmaf(w.z, v, a.z);
        a.w = fmaf(w.w, v, a.w);
    }

    // Streaming store: written once, never re-read.
    __stcs(orow + c, a);

    // Tail columns 256, 257 (chunk 3 only): warp w reduces column 256+w.
    if (chunk == 3) {
        const int  w    = tid >> 5;            // warp id 0/1 -> column 256/257
        const int  lane = tid & 31;
        const int  cc   = 256 + w;
        const int2 ov   = sOV[lane];
        const float4 wt = __ldg(W4 + ov.x + cc);
        const float  v  = __int_as_float(ov.y);
        float tx = wt.x * v, ty = wt.y * v, tz = wt.z * v, tw = wt.w * v;
        #pragma unroll
        for (int off = 16; off >= 1; off >>= 1) {
            tx += __shfl_xor_sync(0xffffffffu, tx, off);
            ty += __shfl_xor_sync(0xffffffffu, ty, off);
            tz += __shfl_xor_sync(0xffffffffu, tz, off);
            tw += __shfl_xor_sync(0xffffffffu, tw, off);
        }
        if (lane == 0) {
            const float4 b = bias4[cc];
            __stcs(orow + cc,
                   make_float4(b.x + tx, b.y + ty, b.z + tz, b.w + tw));
        }
    }
}

extern "C" void kernel_launch(void* const* d_in, const int* in_sizes, int n_in,
                              void* d_out, int out_size)
{
    // metadata order:
    //   0: feature_indices_0  int32  [4096, 32]
    //   1: feature_values_0   f32    [4096, 32]
    //   2: feature_indices_1  int32  [4096, 32]
    //   3: feature_values_1   f32    [4096, 32]
    //   4: merged_weight      f32    [45056, 1032]
    //   5: bias               f32    [1032]
    const int*    idx0 = (const int*)   d_in[0];
    const float*  val0 = (const float*) d_in[1];
    const int*    idx1 = (const int*)   d_in[2];
    const float*  val1 = (const float*) d_in[3];
    const float4* W4   = (const float4*)d_in[4];
    const float4* b4   = (const float4*)d_in[5];

    float4* out = (float4*)d_out;   // [8192, 1032] : out0 then out1

    dim3 grid(2 * BATCH, NCHUNK);
    ft_occ2_kernel<<<grid, THREADS>>>(idx0, val0, idx1, val1, W4, b4, out);
}

// round 15
// speedup vs baseline: 1.1246x; 1.1246x over previous
#include <cuda_runtime.h>

#define NUM_OUTPUTS 1032
#define D4 258              // 1032 floats = 258 float4 per weight row
#define CHUNK 64            // float4 per column chunk; 4 chunks cover 256, +2 tail
#define NCHUNK 4
#define MAX_ACTIVE 32
#define BATCH 4096
#define THREADS 64          // 2 warps, all lanes active
#define MINBLOCKS 32        // hard-pin 32 regs: 65536/(64*32) = 32 -> full occupancy

__global__ __launch_bounds__(THREADS, MINBLOCKS)
void ft_occ3_kernel(const int*    __restrict__ idx0,
                    const float*  __restrict__ val0,
                    const int*    __restrict__ idx1,
                    const float*  __restrict__ val1,
                    const float4* __restrict__ W4,
                    const float4* __restrict__ bias4,
                    float4*       __restrict__ out4)
{
    const int r     = blockIdx.x;          // 0..8191 : both feature sets fused
    const int chunk = blockIdx.y;          // 0..3    : slow dim -> L2 phases
    const int tid   = threadIdx.x;

    const int*   idx;
    const float* val;
    int row;
    if (r < BATCH) { idx = idx0; val = val0; row = r; }
    else           { idx = idx1; val = val1; row = r - BATCH; }

    __shared__ int   sOff[MAX_ACTIVE];     // row offsets in float4 units (fits int)
    __shared__ float sVal[MAX_ACTIVE];
    if (tid < MAX_ACTIVE) {
        sOff[tid] = idx[row * MAX_ACTIVE + tid] * D4;
        sVal[tid] = val[row * MAX_ACTIVE + tid];
    }
    __syncthreads();

    const int c = chunk * CHUNK + tid;     // float4 column index, 0..255
    const float4* __restrict__ Wc = W4 + c;

    float4 a = bias4[c];

    #pragma unroll 8
    for (int k = 0; k < MAX_ACTIVE; ++k) {
        const float4 w = __ldg(Wc + sOff[k]);
        const float  v = sVal[k];
        a.x = fmaf(w.x, v, a.x);
        a.y = fmaf(w.y, v, a.y);
        a.z = fmaf(w.z, v, a.z);
        a.w = fmaf(w.w, v, a.w);
    }

    // Streaming store: written once, never re-read.
    __stcs(out4 + (size_t)r * D4 + c, a);

    // Tail columns 256, 257 (chunk 3 only): warp w reduces column 256+w.
    // Lane l contributes term k=l; butterfly-shfl sum; lane 0 stores.
    if (chunk == 3) {
        const int  w    = tid >> 5;            // warp id 0/1 -> column 256/257
        const int  lane = tid & 31;
        const int  cc   = 256 + w;
        const float4 wt = __ldg(W4 + sOff[lane] + cc);
        const float  v  = sVal[lane];
        float tx = wt.x * v, ty = wt.y * v, tz = wt.z * v, tw = wt.w * v;
        #pragma unroll
        for (int off = 16; off >= 1; off >>= 1) {
            tx += __shfl_xor_sync(0xffffffffu, tx, off);
            ty += __shfl_xor_sync(0xffffffffu, ty, off);
            tz += __shfl_xor_sync(0xffffffffu, tz, off);
            tw += __shfl_xor_sync(0xffffffffu, tw, off);
        }
        if (lane == 0) {
            const float4 b = bias4[cc];
            __stcs(out4 + (size_t)r * D4 + cc,
                   make_float4(b.x + tx, b.y + ty, b.z + tz, b.w + tw));
        }
    }
}

extern "C" void kernel_launch(void* const* d_in, const int* in_sizes, int n_in,
                              void* d_out, int out_size)
{
    // metadata order:
    //   0: feature_indices_0  int32  [4096, 32]
    //   1: feature_values_0   f32    [4096, 32]
    //   2: feature_indices_1  int32  [4096, 32]
    //   3: feature_values_1   f32    [4096, 32]
    //   4: merged_weight      f32    [45056, 1032]
    //   5: bias               f32    [1032]
    const int*    idx0 = (const int*)   d_in[0];
    const float*  val0 = (const float*) d_in[1];
    const int*    idx1 = (const int*)   d_in[2];
    const float*  val1 = (const float*) d_in[3];
    const float4* W4   = (const float4*)d_in[4];
    const float4* b4   = (const float4*)d_in[5];

    float4* out = (float4*)d_out;   // [8192, 1032] : out0 then out1

    dim3 grid(2 * BATCH, NCHUNK);
    ft_occ3_kernel<<<grid, THREADS>>>(idx0, val0, idx1, val1, W4, b4, out);
}